// round 2
// baseline (speedup 1.0000x reference)
#include <cuda_runtime.h>

// SSIM loss, B=64, 1x512x512 fp32, 11x11 uniform box filter, zero padding.
// R1: CHUNK 32 -> 16 (2048 warps, 512 CTAs x 128 thr) to fix latency-bound
// launch shape (was 128 CTAs on 148 SMs, 20 SMs idle, 2 warps/SMSP).
//  - vertical running box sums per column in registers
//  - horizontal sliding window per lane, +-5 col halo via warp shuffles
//  - SSIM map + per-thread accumulate, warp reduce, atomicAdd(double)

namespace {
constexpr int Hh = 512;
constexpr int Ww = 512;
constexpr int Bb = 64;
constexpr int CHUNK = 16;                 // output rows per warp
constexpr int NCHUNK = Hh / CHUNK;        // 32
constexpr float C1c = 0.01f * 0.01f;
constexpr float C2c = 0.03f * 0.03f;
constexpr float INV121 = 1.0f / 121.0f;
}

__device__ double g_acc;

__global__ void k_reset() { g_acc = 0.0; }

__global__ void k_final(float* out) {
    out[0] = (float)(1.0 - g_acc * (1.0 / ((double)Bb * Hh * Ww)));
}

__global__ void __launch_bounds__(128)
k_ssim(const float* __restrict__ X, const float* __restrict__ Y) {
    const int gwarp = (blockIdx.x * blockDim.x + threadIdx.x) >> 5;
    const int lane  = threadIdx.x & 31;
    const int batch = gwarp >> 5;               // / NCHUNK (=32)
    const int chunk = gwarp & (NCHUNK - 1);
    const int row0  = chunk * CHUNK;
    const int c0    = lane << 4;                // 16 cols per lane
    const float* xb = X + batch * (Hh * Ww) + c0;
    const float* yb = Y + batch * (Hh * Ww) + c0;

    // Vertical running sums for 5 channels, 16 columns each (registers).
    float vx[16], vy[16], vxx[16], vyy[16], vxy[16];
#pragma unroll
    for (int k = 0; k < 16; k++) { vx[k] = vy[k] = vxx[k] = vyy[k] = vxy[k] = 0.f; }

    const int lvmin  = (row0 - 5 > 0) ? (row0 - 5) : 0;
    const float lmask = (lane == 0)  ? 0.f : 1.f;   // left image border -> zero pad
    const float rmask = (lane == 31) ? 0.f : 1.f;   // right image border -> zero pad
    float acc = 0.f;

#define VADD(k, xs, ys) do { float _x=(xs), _y=(ys); \
    vx[k]+=_x; vy[k]+=_y; \
    vxx[k]=fmaf(_x,_x,vxx[k]); vyy[k]=fmaf(_y,_y,vyy[k]); vxy[k]=fmaf(_x,_y,vxy[k]); } while(0)
#define VSUB(k, xs, ys) do { float _x=(xs), _y=(ys); \
    vx[k]-=_x; vy[k]-=_y; \
    vxx[k]=fmaf(-_x,_x,vxx[k]); vyy[k]=fmaf(-_y,_y,vyy[k]); vxy[k]=fmaf(-_x,_y,vxy[k]); } while(0)
#define ROW_APPLY(OP) \
    OP(0,a0.x,b0.x);  OP(1,a0.y,b0.y);  OP(2,a0.z,b0.z);  OP(3,a0.w,b0.w); \
    OP(4,a1.x,b1.x);  OP(5,a1.y,b1.y);  OP(6,a1.z,b1.z);  OP(7,a1.w,b1.w); \
    OP(8,a2.x,b2.x);  OP(9,a2.y,b2.y);  OP(10,a2.z,b2.z); OP(11,a2.w,b2.w); \
    OP(12,a3.x,b3.x); OP(13,a3.y,b3.y); OP(14,a3.z,b3.z); OP(15,a3.w,b3.w);

    for (int ri = row0 - 5; ri <= row0 + CHUNK + 4; ++ri) {
        // entering row
        if (ri >= 0 && ri < Hh) {
            const float4* xr = reinterpret_cast<const float4*>(xb + ri * Ww);
            const float4* yr = reinterpret_cast<const float4*>(yb + ri * Ww);
            float4 a0 = xr[0], a1 = xr[1], a2 = xr[2], a3 = xr[3];
            float4 b0 = yr[0], b1 = yr[1], b2 = yr[2], b3 = yr[3];
            ROW_APPLY(VADD)
        }
        // leaving row (only rows that were actually accumulated)
        const int lv = ri - 11;
        if (lv >= lvmin) {
            const float4* xr = reinterpret_cast<const float4*>(xb + lv * Ww);
            const float4* yr = reinterpret_cast<const float4*>(yb + lv * Ww);
            float4 a0 = xr[0], a1 = xr[1], a2 = xr[2], a3 = xr[3];
            float4 b0 = yr[0], b1 = yr[1], b2 = yr[2], b3 = yr[3];
            ROW_APPLY(VSUB)
        }
        // output row ro = ri - 5 once the window is full
        if (ri >= row0 + 5) {
            // halo exchange: left needs lane-1's cols 11..15, right needs lane+1's cols 0..4
            float lx[5], ly[5], lxx[5], lyy[5], lxy[5];
            float rx[5], ry[5], rxx[5], ryy[5], rxy[5];
#pragma unroll
            for (int j = 0; j < 5; j++) {
                lx[j]  = __shfl_up_sync(0xffffffffu, vx[11+j],  1) * lmask;
                ly[j]  = __shfl_up_sync(0xffffffffu, vy[11+j],  1) * lmask;
                lxx[j] = __shfl_up_sync(0xffffffffu, vxx[11+j], 1) * lmask;
                lyy[j] = __shfl_up_sync(0xffffffffu, vyy[11+j], 1) * lmask;
                lxy[j] = __shfl_up_sync(0xffffffffu, vxy[11+j], 1) * lmask;
                rx[j]  = __shfl_down_sync(0xffffffffu, vx[j],  1) * rmask;
                ry[j]  = __shfl_down_sync(0xffffffffu, vy[j],  1) * rmask;
                rxx[j] = __shfl_down_sync(0xffffffffu, vxx[j], 1) * rmask;
                ryy[j] = __shfl_down_sync(0xffffffffu, vyy[j], 1) * rmask;
                rxy[j] = __shfl_down_sync(0xffffffffu, vxy[j], 1) * rmask;
            }
#define HINIT(ch) (l##ch[0]+l##ch[1]+l##ch[2]+l##ch[3]+l##ch[4] \
                  +v##ch[0]+v##ch[1]+v##ch[2]+v##ch[3]+v##ch[4]+v##ch[5])
            float sx  = HINIT(x);
            float sy  = HINIT(y);
            float sxx = HINIT(xx);
            float syy = HINIT(yy);
            float sxy = HINIT(xy);
#undef HINIT
            // sliding: S_{j+1} = S_j + val[j+6] - val[j-5]
#define HADD(ch) ( (j+6 <= 15) ? v##ch[(j+6)&15] : r##ch[((j-10)<0)?0:(j-10)] )
#define HSUB(ch) ( (j >= 5)    ? v##ch[(j-5)&15] : l##ch[(j<5)?j:4] )
#pragma unroll
            for (int j = 0; j < 16; j++) {
                float mux = sx  * INV121;
                float muy = sy  * INV121;
                float exx = sxx * INV121;
                float eyy = syy * INV121;
                float exy = sxy * INV121;
                float mxy = mux * muy;
                float m2  = fmaf(mux, mux, muy * muy);
                float num = fmaf(2.f, mxy, C1c) * fmaf(2.f, exy - mxy, C2c);
                float den = (m2 + C1c) * ((exx + eyy) - m2 + C2c);
                acc += __fdividef(num, den);
                if (j < 15) {
                    sx  += HADD(x)  - HSUB(x);
                    sy  += HADD(y)  - HSUB(y);
                    sxx += HADD(xx) - HSUB(xx);
                    syy += HADD(yy) - HSUB(yy);
                    sxy += HADD(xy) - HSUB(xy);
                }
            }
#undef HADD
#undef HSUB
        }
    }

    // warp reduce, one double atomic per warp
#pragma unroll
    for (int off = 16; off; off >>= 1)
        acc += __shfl_xor_sync(0xffffffffu, acc, off);
    if (lane == 0) atomicAdd(&g_acc, (double)acc);
}

extern "C" void kernel_launch(void* const* d_in, const int* in_sizes, int n_in,
                              void* d_out, int out_size) {
    const float* x = (const float*)d_in[0];
    const float* y = (const float*)d_in[1];
    (void)in_sizes; (void)n_in; (void)out_size;
    k_reset<<<1, 1>>>();
    const int total_warps = Bb * NCHUNK;          // 2048
    k_ssim<<<total_warps / 4, 128>>>(x, y);       // 512 CTAs x 4 warps
    k_final<<<1, 1>>>((float*)d_out);
}

// round 3
// speedup vs baseline: 1.0862x; 1.0862x over previous
#include <cuda_runtime.h>

// SSIM loss, B=64, 1x512x512 fp32, 11x11 box filter, zero padding.
// R2: f32x2 packed math (channel-pair packing), rescaled SSIM algebra
// (x121^4, removes per-px normalization), single kernel with last-CTA
// finalize. CHUNK=32 (best measured shape).

typedef unsigned long long u64;

__device__ __forceinline__ u64 pk2(float lo, float hi) {
    u64 r; asm("mov.b64 %0, {%1, %2};" : "=l"(r) : "f"(lo), "f"(hi)); return r;
}
__device__ __forceinline__ void upk2(u64 v, float& lo, float& hi) {
    asm("mov.b64 {%0, %1}, %2;" : "=f"(lo), "=f"(hi) : "l"(v));
}
__device__ __forceinline__ u64 add2(u64 a, u64 b) {
    u64 r; asm("add.rn.f32x2 %0, %1, %2;" : "=l"(r) : "l"(a), "l"(b)); return r;
}
__device__ __forceinline__ u64 mul2(u64 a, u64 b) {
    u64 r; asm("mul.rn.f32x2 %0, %1, %2;" : "=l"(r) : "l"(a), "l"(b)); return r;
}
__device__ __forceinline__ u64 fma2(u64 a, u64 b, u64 c) {
    u64 r; asm("fma.rn.f32x2 %0, %1, %2, %3;" : "=l"(r) : "l"(a), "l"(b), "l"(c)); return r;
}

namespace {
constexpr int Hh = 512;
constexpr int Ww = 512;
constexpr int Bb = 64;
constexpr int CHUNK = 32;                  // output rows per warp
constexpr int NCHUNK = Hh / CHUNK;         // 16
constexpr int NWARP = Bb * NCHUNK;         // 1024
constexpr int BLK = 128;                   // 4 warps/CTA
constexpr int NCTA = NWARP * 32 / BLK;     // 256
// SSIM rescaled by S^4, S=121: C1*S^2, C2*S^2
constexpr float C1S = 0.0001f * 14641.0f;  // 1.4641
constexpr float C2S = 0.0009f * 14641.0f;  // 13.1769
}

__device__ double g_acc;       // zero-initialized at module load; restored by last CTA
__device__ int    g_count;

__global__ void __launch_bounds__(BLK)
k_ssim(const float* __restrict__ X, const float* __restrict__ Y, float* __restrict__ out) {
    const int gwarp = (blockIdx.x * BLK + threadIdx.x) >> 5;
    const int lane  = threadIdx.x & 31;
    const int batch = gwarp >> 4;              // / NCHUNK
    const int chunk = gwarp & (NCHUNK - 1);
    const int row0  = chunk * CHUNK;
    const int c0    = lane << 4;               // 16 cols per lane
    const float* xb = X + batch * (Hh * Ww) + c0;
    const float* yb = Y + batch * (Hh * Ww) + c0;

    const u64 KN1 = pk2(-1.f, -1.f);
    const float lmask = (lane == 0)  ? 0.f : 1.f;
    const float rmask = (lane == 31) ? 0.f : 1.f;
    const u64 lmask2 = pk2(lmask, lmask);
    const u64 rmask2 = pk2(rmask, rmask);

    // per-column running sums: packed (sum_x, sum_y), packed (sum_xx, sum_yy), scalar sum_xy
    u64 vab[16], vsq[16];
    float vxy[16];
#pragma unroll
    for (int k = 0; k < 16; k++) { vab[k] = 0ull; vsq[k] = 0ull; vxy[k] = 0.f; }

    const int lvmin = (row0 - 5 > 0) ? (row0 - 5) : 0;
    float acc = 0.f;

#define VENT(k, xs, ys) do { float _x=(xs), _y=(ys); u64 _p=pk2(_x,_y); \
    vab[k]=add2(vab[k],_p); vsq[k]=fma2(_p,_p,vsq[k]); vxy[k]=fmaf(_x,_y,vxy[k]); } while(0)
#define VLEA(k, xs, ys) do { float _x=(xs), _y=(ys); u64 _p=pk2(_x,_y); u64 _n=mul2(_p,KN1); \
    vab[k]=add2(vab[k],_n); vsq[k]=fma2(_n,_p,vsq[k]); vxy[k]=fmaf(-_x,_y,vxy[k]); } while(0)
#define ROW_APPLY(OP) \
    OP(0,a0.x,b0.x);  OP(1,a0.y,b0.y);  OP(2,a0.z,b0.z);  OP(3,a0.w,b0.w); \
    OP(4,a1.x,b1.x);  OP(5,a1.y,b1.y);  OP(6,a1.z,b1.z);  OP(7,a1.w,b1.w); \
    OP(8,a2.x,b2.x);  OP(9,a2.y,b2.y);  OP(10,a2.z,b2.z); OP(11,a2.w,b2.w); \
    OP(12,a3.x,b3.x); OP(13,a3.y,b3.y); OP(14,a3.z,b3.z); OP(15,a3.w,b3.w);

    for (int ri = row0 - 5; ri <= row0 + CHUNK + 4; ++ri) {
        if (ri >= 0 && ri < Hh) {                      // entering row
            const float4* xr = reinterpret_cast<const float4*>(xb + ri * Ww);
            const float4* yr = reinterpret_cast<const float4*>(yb + ri * Ww);
            float4 a0 = xr[0], a1 = xr[1], a2 = xr[2], a3 = xr[3];
            float4 b0 = yr[0], b1 = yr[1], b2 = yr[2], b3 = yr[3];
            ROW_APPLY(VENT)
        }
        const int lv = ri - 11;                        // leaving row
        if (lv >= lvmin) {
            const float4* xr = reinterpret_cast<const float4*>(xb + lv * Ww);
            const float4* yr = reinterpret_cast<const float4*>(yb + lv * Ww);
            float4 a0 = xr[0], a1 = xr[1], a2 = xr[2], a3 = xr[3];
            float4 b0 = yr[0], b1 = yr[1], b2 = yr[2], b3 = yr[3];
            ROW_APPLY(VLEA)
        }
        if (ri >= row0 + 5) {                          // emit output row ri-5
            // halo exchange via 32-bit shuffles of packed halves
            u64 lab[5], lsq[5], rab[5], rsq[5];
            float lxy[5], rxy[5];
#pragma unroll
            for (int j = 0; j < 5; j++) {
                float a, b;
                upk2(vab[11 + j], a, b);
                lab[j] = mul2(pk2(__shfl_up_sync(0xffffffffu, a, 1),
                                  __shfl_up_sync(0xffffffffu, b, 1)), lmask2);
                upk2(vsq[11 + j], a, b);
                lsq[j] = mul2(pk2(__shfl_up_sync(0xffffffffu, a, 1),
                                  __shfl_up_sync(0xffffffffu, b, 1)), lmask2);
                lxy[j] = __shfl_up_sync(0xffffffffu, vxy[11 + j], 1) * lmask;
                upk2(vab[j], a, b);
                rab[j] = mul2(pk2(__shfl_down_sync(0xffffffffu, a, 1),
                                  __shfl_down_sync(0xffffffffu, b, 1)), rmask2);
                upk2(vsq[j], a, b);
                rsq[j] = mul2(pk2(__shfl_down_sync(0xffffffffu, a, 1),
                                  __shfl_down_sync(0xffffffffu, b, 1)), rmask2);
                rxy[j] = __shfl_down_sync(0xffffffffu, vxy[j], 1) * rmask;
            }
            // window init for col j=0: l[0..4] + v[0..5]
#define HIN2(L, V) add2(add2(add2(add2(L[0],L[1]), add2(L[2],L[3])), \
                             add2(add2(L[4],V[0]), add2(V[1],V[2]))), \
                        add2(add2(V[3],V[4]), V[5]))
            u64 sab = HIN2(lab, vab);
            u64 ssq = HIN2(lsq, vsq);
            float sxy = ((lxy[0]+lxy[1]) + (lxy[2]+lxy[3])) + ((lxy[4]+vxy[0]) + (vxy[1]+vxy[2]))
                      + ((vxy[3]+vxy[4]) + vxy[5]);
#undef HIN2
#define HADD(A, R) ((j + 6 <= 15) ? A[(j + 6) & 15] : R[((j - 10) < 0) ? 0 : (j - 10)])
#define HSUB(A, L) ((j >= 5) ? A[(j - 5) & 15] : L[(j < 5) ? j : 4])
#pragma unroll
            for (int j = 0; j < 16; j++) {
                float sx, sy, sxx, syy;
                upk2(sab, sx, sy);
                upk2(ssq, sxx, syy);
                float pxy = sx * sy;
                float qx, qy;
                upk2(mul2(sab, sab), qx, qy);
                float m2   = qx + qy;                    // sx^2 + sy^2
                float esum = sxx + syy;
                float t1   = fmaf(2.f, pxy, C1S);        // 2*sx*sy + C1*S^2
                float t2   = fmaf(242.f, sxy, fmaf(-2.f, pxy, C2S)); // 2(S*sxy - pxy)+C2*S^2
                float num  = t1 * t2;
                float den1 = m2 + C1S;
                float den2 = fmaf(121.f, esum, C2S - m2);
                acc += __fdividef(num, den1 * den2);
                if (j < 15) {
                    sab = add2(sab, HADD(vab, rab));
                    sab = fma2(HSUB(vab, lab), KN1, sab);
                    ssq = add2(ssq, HADD(vsq, rsq));
                    ssq = fma2(HSUB(vsq, lsq), KN1, ssq);
                    sxy += HADD(vxy, rxy) - HSUB(vxy, lxy);
                }
            }
#undef HADD
#undef HSUB
        }
    }

    // warp reduce, one double atomic per warp
#pragma unroll
    for (int off = 16; off; off >>= 1)
        acc += __shfl_xor_sync(0xffffffffu, acc, off);
    if (lane == 0) atomicAdd(&g_acc, (double)acc);

    // last-CTA finalize: write result, restore globals for next graph replay
    __syncthreads();
    if (threadIdx.x == 0) {
        __threadfence();
        int old = atomicAdd(&g_count, 1);
        if (old == NCTA - 1) {
            double total = g_acc;
            out[0] = (float)(1.0 - total * (1.0 / ((double)Bb * Hh * Ww)));
            g_acc = 0.0;
            g_count = 0;
        }
    }
}

extern "C" void kernel_launch(void* const* d_in, const int* in_sizes, int n_in,
                              void* d_out, int out_size) {
    const float* x = (const float*)d_in[0];
    const float* y = (const float*)d_in[1];
    (void)in_sizes; (void)n_in; (void)out_size;
    k_ssim<<<NCTA, BLK>>>(x, y, (float*)d_out);
}